// round 1
// baseline (speedup 1.0000x reference)
#include <cuda_runtime.h>

#define BB 64
#define NN 4096
#define DD 128
#define NS 8
#define SCALE 0.08838834764831845f

// ---------------- device scratch (no allocations allowed) ----------------
__device__ float g_keys[BB*NN*DD];   // 134 MB
__device__ float g_vals[BB*NN*DD];   // 134 MB
__device__ float g_attn[BB*NS*NN];   // 8 MB
__device__ float g_q[BB*NS*DD];
__device__ float g_slots[BB*NS*DD];
__device__ float g_upd[BB*NS*DD];
__device__ float g_rs[BB*NS];

__global__ __launch_bounds__(256) void init_slots_kernel(const float* __restrict__ src){
    int i = blockIdx.x*256 + threadIdx.x;
    g_slots[i] = src[i];
}
__global__ __launch_bounds__(256) void export_kernel(float* __restrict__ dst){
    int i = blockIdx.x*256 + threadIdx.x;
    dst[i] = g_slots[i];
}

// ---------------- kernel 1: LN(x) fused with K/V projection ----------------
// Block: 256 threads, 64 rows of x -> keys[64,128], vals[64,128].
// C[64,256] = Xn[64,128] @ Wall^T, register tile 8x8 per thread.
__global__ __launch_bounds__(256) void ln_kv_kernel(
    const float* __restrict__ x,
    const float* __restrict__ Wk, const float* __restrict__ bk,
    const float* __restrict__ Wv, const float* __restrict__ bv,
    const float* __restrict__ gin, const float* __restrict__ bin)
{
    __shared__ float xs[64*128];   // 32 KB normalized input tile
    __shared__ float wst[8*256];   // 8 KB  W chunk, transposed [kk][c]
    const int tid = threadIdx.x;

    // ---- LayerNorm phase: 4 threads per row, 32 elems each ----
    {
        const int row = tid >> 2, seg = tid & 3;
        const float4* xp = (const float4*)(x + (blockIdx.x*64 + row)*128) + seg*8;
        float4 v[8];
        float s = 0.f, ss = 0.f;
        #pragma unroll
        for (int j = 0; j < 8; j++){
            v[j] = xp[j];
            s  += v[j].x + v[j].y + v[j].z + v[j].w;
            ss += v[j].x*v[j].x + v[j].y*v[j].y + v[j].z*v[j].z + v[j].w*v[j].w;
        }
        s  += __shfl_xor_sync(0xffffffffu, s, 1);
        ss += __shfl_xor_sync(0xffffffffu, ss, 1);
        s  += __shfl_xor_sync(0xffffffffu, s, 2);
        ss += __shfl_xor_sync(0xffffffffu, ss, 2);
        const float m = s * (1.f/128.f);
        const float rstd = rsqrtf(ss*(1.f/128.f) - m*m + 1e-5f);
        const float4* g4p = (const float4*)gin + seg*8;
        const float4* b4p = (const float4*)bin + seg*8;
        #pragma unroll
        for (int j = 0; j < 8; j++){
            float4 g4 = g4p[j], b4 = b4p[j], o;
            o.x = (v[j].x - m)*rstd*g4.x + b4.x;
            o.y = (v[j].y - m)*rstd*g4.y + b4.y;
            o.z = (v[j].z - m)*rstd*g4.z + b4.z;
            o.w = (v[j].w - m)*rstd*g4.w + b4.w;
            *(float4*)(xs + row*128 + seg*32 + j*4) = o;
        }
    }

    const int cg = tid & 31, rg = tid >> 5;
    float acc[8][8];
    #pragma unroll
    for (int j = 0; j < 8; j++){
        int c = cg + 32*j;
        float b = (c < 128) ? bk[c] : bv[c-128];
        #pragma unroll
        for (int i = 0; i < 8; i++) acc[i][j] = b;
    }

    for (int k0 = 0; k0 < 128; k0 += 8){
        __syncthreads();
        {   // stage W chunk transposed: wst[kk][c], c: 0..127 keys, 128..255 vals
            const float* wr = (tid < 128) ? (Wk + tid*128 + k0) : (Wv + (tid-128)*128 + k0);
            float4 w0 = *(const float4*)(wr);
            float4 w1 = *(const float4*)(wr+4);
            wst[0*256+tid]=w0.x; wst[1*256+tid]=w0.y; wst[2*256+tid]=w0.z; wst[3*256+tid]=w0.w;
            wst[4*256+tid]=w1.x; wst[5*256+tid]=w1.y; wst[6*256+tid]=w1.z; wst[7*256+tid]=w1.w;
        }
        __syncthreads();
        #pragma unroll
        for (int kk = 0; kk < 8; kk += 4){
            float4 a4[8];
            #pragma unroll
            for (int i = 0; i < 8; i++)           // broadcast loads (warp-uniform)
                a4[i] = *(const float4*)(xs + (rg+8*i)*128 + k0 + kk);
            #pragma unroll
            for (int q = 0; q < 4; q++){
                float b[8];
                #pragma unroll
                for (int j = 0; j < 8; j++) b[j] = wst[(kk+q)*256 + cg + 32*j];
                #pragma unroll
                for (int i = 0; i < 8; i++){
                    float a = (q==0)?a4[i].x:(q==1)?a4[i].y:(q==2)?a4[i].z:a4[i].w;
                    #pragma unroll
                    for (int j = 0; j < 8; j++) acc[i][j] += a*b[j];
                }
            }
        }
    }

    #pragma unroll
    for (int i = 0; i < 8; i++){
        int gr = blockIdx.x*64 + rg + 8*i;
        #pragma unroll
        for (int j = 0; j < 8; j++){
            int c = cg + 32*j;
            if (c < 128) g_keys[gr*128 + c]       = acc[i][j];
            else         g_vals[gr*128 + (c-128)] = acc[i][j];
        }
    }
}

// ---------------- kernel 2: slot LN + q projection (scale folded in) ----------------
__global__ __launch_bounds__(128) void slot_q_kernel(
    const float* __restrict__ Wq, const float* __restrict__ bq,
    const float* __restrict__ gs, const float* __restrict__ bs)
{
    __shared__ float sn[128];
    __shared__ float red[8];
    const int row = blockIdx.x, tid = threadIdx.x;
    const int lane = tid & 31, wid = tid >> 5;
    float v = g_slots[row*128 + tid];
    float s = v, ss = v*v;
    #pragma unroll
    for (int o = 16; o; o >>= 1){
        s  += __shfl_xor_sync(0xffffffffu, s, o);
        ss += __shfl_xor_sync(0xffffffffu, ss, o);
    }
    if (lane == 0){ red[wid] = s; red[4+wid] = ss; }
    __syncthreads();
    s  = red[0]+red[1]+red[2]+red[3];
    ss = red[4]+red[5]+red[6]+red[7];
    float m = s*(1.f/128.f);
    float rstd = rsqrtf(ss*(1.f/128.f) - m*m + 1e-5f);
    sn[tid] = (v - m)*rstd*gs[tid] + bs[tid];
    g_upd[row*128 + tid] = 0.f;     // zero accumulators for this iteration
    if (tid == 0) g_rs[row] = 0.f;
    __syncthreads();
    float acc = bq[tid];
    const float4* wr  = (const float4*)(Wq + tid*128);
    const float4* sn4 = (const float4*)sn;
    #pragma unroll
    for (int e = 0; e < 32; e++){
        float4 w = wr[e], q = sn4[e];
        acc += w.x*q.x + w.y*q.y + w.z*q.z + w.w*q.w;
    }
    g_q[row*128 + tid] = acc * SCALE;
}

// ---------------- kernel 3: logits + softmax over slots + rowsum partials ----------------
// one thread per token n; 128 tokens per block; grid = B * 32
__global__ __launch_bounds__(128) void attn_kernel()
{
    __shared__ float qs[NS*DD];
    __shared__ float srs[NS];
    const int tid = threadIdx.x;
    const int bb = blockIdx.x >> 5;
    const int n0 = (blockIdx.x & 31) * 128;
    #pragma unroll
    for (int r = 0; r < 8; r++) qs[r*128 + tid] = g_q[bb*1024 + r*128 + tid];
    if (tid < 8) srs[tid] = 0.f;
    __syncthreads();

    float l[8];
    #pragma unroll
    for (int i = 0; i < 8; i++) l[i] = 0.f;
    const float4* krow = (const float4*)(g_keys + (bb*4096 + n0 + tid)*128);
    const float4* q4 = (const float4*)qs;
    #pragma unroll 4
    for (int e = 0; e < 32; e++){
        float4 kv = krow[e];
        #pragma unroll
        for (int i = 0; i < 8; i++){
            float4 qv = q4[i*32 + e];   // warp-uniform broadcast
            l[i] += kv.x*qv.x + kv.y*qv.y + kv.z*qv.z + kv.w*qv.w;
        }
    }
    float mx = l[0];
    #pragma unroll
    for (int i = 1; i < 8; i++) mx = fmaxf(mx, l[i]);
    float sum = 0.f;
    #pragma unroll
    for (int i = 0; i < 8; i++){ l[i] = __expf(l[i]-mx); sum += l[i]; }
    float inv = 1.f/sum;
    const int base = bb*NS*NN + n0 + tid;
    #pragma unroll
    for (int i = 0; i < 8; i++){
        float p = l[i]*inv + 1e-8f;
        g_attn[base + i*NN] = p;
        l[i] = p;
    }
    #pragma unroll
    for (int i = 0; i < 8; i++){
        float r = l[i];
        #pragma unroll
        for (int o = 16; o; o >>= 1) r += __shfl_xor_sync(0xffffffffu, r, o);
        if ((tid & 31) == 0) atomicAdd(&srs[i], r);
    }
    __syncthreads();
    if (tid < 8) atomicAdd(&g_rs[bb*8 + tid], srs[tid]);
}

// ---------------- kernel 4: updates = (attn @ V) / rowsum ----------------
// one thread per d; 256-token chunks; grid = B * 16
__global__ __launch_bounds__(128) void upd_kernel()
{
    __shared__ float att_s[8][256];
    __shared__ float rsv[8];
    const int tid = threadIdx.x;
    const int bb = blockIdx.x >> 4;
    const int n0 = (blockIdx.x & 15) * 256;
    #pragma unroll
    for (int i = 0; i < 8; i++){
        att_s[i][tid]     = g_attn[bb*NS*NN + i*NN + n0 + tid];
        att_s[i][tid+128] = g_attn[bb*NS*NN + i*NN + n0 + tid + 128];
    }
    if (tid < 8) rsv[tid] = g_rs[bb*8 + tid];
    __syncthreads();
    float acc[8];
    #pragma unroll
    for (int i = 0; i < 8; i++) acc[i] = 0.f;
    const float* vp = g_vals + (bb*4096 + n0)*128 + tid;
    #pragma unroll 2
    for (int n = 0; n < 256; n += 4){
        float v0 = vp[(n+0)*128];
        float v1 = vp[(n+1)*128];
        float v2 = vp[(n+2)*128];
        float v3 = vp[(n+3)*128];
        #pragma unroll
        for (int i = 0; i < 8; i++){
            const float4 a = *(const float4*)&att_s[i][n];   // broadcast
            acc[i] += a.x*v0 + a.y*v1 + a.z*v2 + a.w*v3;
        }
    }
    #pragma unroll
    for (int i = 0; i < 8; i++)
        atomicAdd(&g_upd[(bb*8+i)*128 + tid], acc[i] / rsv[i]);
}

// ---------------- kernel 5: GRU cell + LN + MLP residual ----------------
// one block per batch b, loops the 8 slots; 128 threads (= one d each)
__global__ __launch_bounds__(128) void gru_mlp_kernel(
    const float* __restrict__ W_ih, const float* __restrict__ W_hh,
    const float* __restrict__ b_ih, const float* __restrict__ b_hh,
    const float* __restrict__ gm, const float* __restrict__ bm,
    const float* __restrict__ W1, const float* __restrict__ b1,
    const float* __restrict__ W2, const float* __restrict__ b2)
{
    __shared__ float us[128], ps[128], hs[128], red[8];
    const int b = blockIdx.x, tid = threadIdx.x;
    const int lane = tid & 31, wid = tid >> 5;
    for (int slot = 0; slot < 8; slot++){
        const int row = b*8 + slot;
        float u = g_upd[row*128 + tid];
        float h = g_slots[row*128 + tid];
        us[tid] = u; ps[tid] = h;
        __syncthreads();
        float gi[3], gh[3];
        #pragma unroll
        for (int g = 0; g < 3; g++){
            const float4* wi = (const float4*)(W_ih + (g*128 + tid)*128);
            const float4* wh = (const float4*)(W_hh + (g*128 + tid)*128);
            float ai = b_ih[g*128 + tid];
            float ah = b_hh[g*128 + tid];
            const float4* u4 = (const float4*)us;
            const float4* p4 = (const float4*)ps;
            #pragma unroll 8
            for (int e = 0; e < 32; e++){
                float4 a = wi[e], uu = u4[e];
                ai += a.x*uu.x + a.y*uu.y + a.z*uu.z + a.w*uu.w;
                float4 c = wh[e], pp = p4[e];
                ah += c.x*pp.x + c.y*pp.y + c.z*pp.z + c.w*pp.w;
            }
            gi[g] = ai; gh[g] = ah;
        }
        float r = 1.f/(1.f + __expf(-(gi[0]+gh[0])));
        float z = 1.f/(1.f + __expf(-(gi[1]+gh[1])));
        float n = tanhf(gi[2] + r*gh[2]);
        float hn = (1.f - z)*n + z*h;
        // LayerNorm(hn)
        float s = hn, ss = hn*hn;
        #pragma unroll
        for (int o = 16; o; o >>= 1){
            s  += __shfl_xor_sync(0xffffffffu, s, o);
            ss += __shfl_xor_sync(0xffffffffu, ss, o);
        }
        if (lane == 0){ red[wid] = s; red[4+wid] = ss; }
        __syncthreads();
        s  = red[0]+red[1]+red[2]+red[3];
        ss = red[4]+red[5]+red[6]+red[7];
        float m = s*(1.f/128.f);
        float rstd = rsqrtf(ss*(1.f/128.f) - m*m + 1e-5f);
        hs[tid] = (hn - m)*rstd*gm[tid] + bm[tid];
        __syncthreads();
        float hid = b1[tid];
        {
            const float4* w  = (const float4*)(W1 + tid*128);
            const float4* h4 = (const float4*)hs;
            #pragma unroll 8
            for (int e = 0; e < 32; e++){
                float4 a = w[e], xx = h4[e];
                hid += a.x*xx.x + a.y*xx.y + a.z*xx.z + a.w*xx.w;
            }
        }
        hid = fmaxf(hid, 0.f);
        us[tid] = hid;
        __syncthreads();
        float out = hn + b2[tid];
        {
            const float4* w  = (const float4*)(W2 + tid*128);
            const float4* h4 = (const float4*)us;
            #pragma unroll 8
            for (int e = 0; e < 32; e++){
                float4 a = w[e], xx = h4[e];
                out += a.x*xx.x + a.y*xx.y + a.z*xx.z + a.w*xx.w;
            }
        }
        g_slots[row*128 + tid] = out;
        __syncthreads();
    }
}

// ---------------- launch ----------------
extern "C" void kernel_launch(void* const* d_in, const int* in_sizes, int n_in,
                              void* d_out, int out_size)
{
    const float* x    = (const float*)d_in[0];
    const float* si   = (const float*)d_in[1];
    const float* Wq   = (const float*)d_in[2];
    const float* bq   = (const float*)d_in[3];
    const float* Wk   = (const float*)d_in[4];
    const float* bk   = (const float*)d_in[5];
    const float* Wv   = (const float*)d_in[6];
    const float* bv   = (const float*)d_in[7];
    const float* gin  = (const float*)d_in[8];
    const float* bin  = (const float*)d_in[9];
    const float* gsl  = (const float*)d_in[10];
    const float* bsl  = (const float*)d_in[11];
    const float* gm   = (const float*)d_in[12];
    const float* bm   = (const float*)d_in[13];
    const float* W1   = (const float*)d_in[14];
    const float* b1   = (const float*)d_in[15];
    const float* W2   = (const float*)d_in[16];
    const float* b2   = (const float*)d_in[17];
    const float* W_ih = (const float*)d_in[18];
    const float* W_hh = (const float*)d_in[19];
    const float* b_ih = (const float*)d_in[20];
    const float* b_hh = (const float*)d_in[21];

    init_slots_kernel<<<256, 256>>>(si);
    ln_kv_kernel<<<4096, 256>>>(x, Wk, bk, Wv, bv, gin, bin);
    for (int it = 0; it < 3; it++){
        slot_q_kernel<<<512, 128>>>(Wq, bq, gsl, bsl);
        attn_kernel<<<2048, 128>>>();
        upd_kernel<<<1024, 128>>>();
        gru_mlp_kernel<<<64, 128>>>(W_ih, W_hh, b_ih, b_hh, gm, bm, W1, b1, W2, b2);
    }
    export_kernel<<<256, 256>>>((float*)d_out);
}

// round 3
// speedup vs baseline: 1.3054x; 1.3054x over previous
#include <cuda_runtime.h>
#include <cuda_bf16.h>
#include <cstdint>

#define BB 64
#define NN 4096
#define DD 128
#define NS 8
#define SCALE 0.08838834764831845f

// ---------------- device scratch ----------------
__device__ float g_keys[BB*NN*DD];   // 134 MB
__device__ float g_vals[BB*NN*DD];   // 134 MB
__device__ float g_attn[BB*NS*NN];   // 8 MB
__device__ float g_q[BB*NS*DD];
__device__ float g_slots[BB*NS*DD];
__device__ float g_upd[BB*NS*DD];
__device__ float g_rs[BB*NS];
// bf16 hi/lo images of [Wk;Wv], pitched rows of 136 elems (272B)
#define WPITCH 136
#define WIMG   (128*WPITCH)          // 17408 elems per image
__device__ __nv_bfloat16 g_w_hi[2*WIMG];
__device__ __nv_bfloat16 g_w_lo[2*WIMG];

__device__ __forceinline__ uint32_t smem_u32(const void* p){
    uint32_t a;
    asm("{ .reg .u64 t; cvta.to.shared.u64 t, %1; cvt.u32.u64 %0, t; }" : "=r"(a) : "l"(p));
    return a;
}

#define LDSM4(r0,r1,r2,r3,addr) \
    asm volatile("ldmatrix.sync.aligned.m8n8.x4.shared.b16 {%0,%1,%2,%3}, [%4];" \
        : "=r"(r0),"=r"(r1),"=r"(r2),"=r"(r3) : "r"(addr))
#define LDSM2(r0,r1,addr) \
    asm volatile("ldmatrix.sync.aligned.m8n8.x2.shared.b16 {%0,%1}, [%2];" \
        : "=r"(r0),"=r"(r1) : "r"(addr))
#define MMA16816(c,a0,a1,a2,a3,b0,b1) \
    asm volatile("mma.sync.aligned.m16n8k16.row.col.f32.bf16.bf16.f32 " \
        "{%0,%1,%2,%3}, {%4,%5,%6,%7}, {%8,%9}, {%0,%1,%2,%3};" \
        : "+f"((c)[0]),"+f"((c)[1]),"+f"((c)[2]),"+f"((c)[3]) \
        : "r"(a0),"r"(a1),"r"(a2),"r"(a3),"r"(b0),"r"(b1))

// SMEM layout (dynamic):
#define S_BIAS  0                        // 256 floats (bk | bv)
#define S_A_HI  1024
#define S_A_LO  (1024 + 34816)
#define S_W     (1024 + 2*34816)         // KH, KL, VH, VL, each 34816 B
#define S_TOTAL (S_W + 4*34816)          // 209920 B
#define APITCHB 272                      // bytes per A/W row (136 bf16)

__global__ __launch_bounds__(256) void init_slots_kernel(const float* __restrict__ src){
    int i = blockIdx.x*256 + threadIdx.x;
    g_slots[i] = src[i];
}
__global__ __launch_bounds__(256) void export_kernel(float* __restrict__ dst){
    int i = blockIdx.x*256 + threadIdx.x;
    dst[i] = g_slots[i];
}

// ---------------- prep: Wk/Wv -> pitched bf16 hi/lo images ----------------
__global__ __launch_bounds__(256) void prep_w_kernel(const float* __restrict__ Wk,
                                                     const float* __restrict__ Wv){
    int i = blockIdx.x*256 + threadIdx.x;     // 0..32767
    int m = i >> 14;
    int idx = i & 16383;
    int row = idx >> 7, k = idx & 127;
    float v = (m ? Wv : Wk)[row*128 + k];
    __nv_bfloat16 h = __float2bfloat16_rn(v);
    __nv_bfloat16 l = __float2bfloat16_rn(v - __bfloat162float(h));
    g_w_hi[m*WIMG + row*WPITCH + k] = h;
    g_w_lo[m*WIMG + row*WPITCH + k] = l;
}

// ---------------- kernel 1: LN(x) + K/V projection via mma.sync bf16x3 ----------------
// grid 2048, 256 threads (8 warps), 128 rows of x per CTA -> keys/vals [128][128]
__global__ __launch_bounds__(256, 1) void ln_kv_mma_kernel(
    const float* __restrict__ x,
    const float* __restrict__ bk, const float* __restrict__ bv,
    const float* __restrict__ gin, const float* __restrict__ bin)
{
    extern __shared__ __align__(1024) char smem[];
    const uint32_t sb = smem_u32(smem);
    const int tid = threadIdx.x;
    const int wid = tid >> 5, lane = tid & 31;

    if (tid < 128){
        ((float*)(smem + S_BIAS))[tid]       = bk[tid];
        ((float*)(smem + S_BIAS))[tid + 128] = bv[tid];
    }

    // ---- copy weight images: KH, KL, VH, VL (each 2176 uint4) ----
    {
        uint4* dst = (uint4*)(smem + S_W);
        const uint4* hi4 = (const uint4*)g_w_hi;
        const uint4* lo4 = (const uint4*)g_w_lo;
        for (int i = tid; i < 2176; i += 256){
            dst[i]        = hi4[i];          // K hi
            dst[2176 + i] = lo4[i];          // K lo
            dst[4352 + i] = hi4[2176 + i];   // V hi
            dst[6528 + i] = lo4[2176 + i];   // V lo
        }
    }

    // ---- LayerNorm: 2 threads per row, 64 cols each; write bf16 hi/lo (pitched) ----
    {
        const int row = tid >> 1, half = tid & 1;
        const float* xr = x + ((size_t)(blockIdx.x*128 + row))*128 + half*64;
        float4 v[16];
        float s = 0.f, ss = 0.f;
        #pragma unroll
        for (int j = 0; j < 16; j++){
            v[j] = ((const float4*)xr)[j];
            s  += v[j].x + v[j].y + v[j].z + v[j].w;
            ss += v[j].x*v[j].x + v[j].y*v[j].y + v[j].z*v[j].z + v[j].w*v[j].w;
        }
        s  += __shfl_xor_sync(0xffffffffu, s, 1);
        ss += __shfl_xor_sync(0xffffffffu, ss, 1);
        const float m = s * (1.f/128.f);
        const float rstd = rsqrtf(ss*(1.f/128.f) - m*m + 1e-5f);
        #pragma unroll
        for (int j = 0; j < 16; j++){
            const int k0 = half*64 + j*4;
            float4 g4 = ((const float4*)gin)[k0>>2];
            float4 b4 = ((const float4*)bin)[k0>>2];
            float n0 = (v[j].x - m)*rstd*g4.x + b4.x;
            float n1 = (v[j].y - m)*rstd*g4.y + b4.y;
            float n2 = (v[j].z - m)*rstd*g4.z + b4.z;
            float n3 = (v[j].w - m)*rstd*g4.w + b4.w;
            __nv_bfloat16 h0 = __float2bfloat16_rn(n0), h1 = __float2bfloat16_rn(n1);
            __nv_bfloat16 h2 = __float2bfloat16_rn(n2), h3 = __float2bfloat16_rn(n3);
            __nv_bfloat162 hA; hA.x = h0; hA.y = h1;
            __nv_bfloat162 hB; hB.x = h2; hB.y = h3;
            __nv_bfloat162 lA, lB;
            lA.x = __float2bfloat16_rn(n0 - __bfloat162float(h0));
            lA.y = __float2bfloat16_rn(n1 - __bfloat162float(h1));
            lB.x = __float2bfloat16_rn(n2 - __bfloat162float(h2));
            lB.y = __float2bfloat16_rn(n3 - __bfloat162float(h3));
            char* ahp = smem + S_A_HI + row*APITCHB + k0*2;
            char* alp = smem + S_A_LO + row*APITCHB + k0*2;
            *(__nv_bfloat162*)(ahp)     = hA;
            *(__nv_bfloat162*)(ahp + 4) = hB;
            *(__nv_bfloat162*)(alp)     = lA;
            *(__nv_bfloat162*)(alp + 4) = lB;
        }
    }
    __syncthreads();

    // ---- per-lane ldmatrix address components ----
    const int aRow  = (lane & 7) + ((lane >> 3) & 1) * 8;    // x4: rows 0..15
    const int aKoff = (lane >> 4) * 16;                      // x4: k halves
    const uint32_t aHiBase = sb + S_A_HI + (16*wid + aRow)*APITCHB + aKoff;
    const uint32_t aLoBase = sb + S_A_LO + (16*wid + aRow)*APITCHB + aKoff;
    const int bRow  = lane & 7;                              // x2: n rows 0..7
    const int bKoff = ((lane >> 3) & 1) * 16;                // x2: k halves
    const float* bias = (const float*)(smem + S_BIAS);
    const size_t gb = (size_t)blockIdx.x * 16384;
    const int r0 = 16*wid + (lane >> 2);
    const int cc = 2*(lane & 3);

    #pragma unroll
    for (int p = 0; p < 4; p++){
        const int isV  = p >> 1;
        const int colb = (p & 1) * 64;
        const uint32_t wHiBase = sb + S_W + isV*69632 + (colb + bRow)*APITCHB + bKoff;
        const uint32_t wLoBase = wHiBase + 34816;

        float acc[8][4];
        #pragma unroll
        for (int nt = 0; nt < 8; nt++){
            acc[nt][0]=0.f; acc[nt][1]=0.f; acc[nt][2]=0.f; acc[nt][3]=0.f;
        }

        #pragma unroll
        for (int kc = 0; kc < 8; kc++){
            const uint32_t ko = kc*32;
            uint32_t ah0,ah1,ah2,ah3, al0,al1,al2,al3;
            LDSM4(ah0,ah1,ah2,ah3, aHiBase + ko);
            LDSM4(al0,al1,al2,al3, aLoBase + ko);
            #pragma unroll
            for (int nt = 0; nt < 8; nt++){
                uint32_t bh0,bh1, bl0,bl1;
                LDSM2(bh0,bh1, wHiBase + nt*(8*APITCHB) + ko);
                LDSM2(bl0,bl1, wLoBase + nt*(8*APITCHB) + ko);
                MMA16816(acc[nt], ah0,ah1,ah2,ah3, bh0,bh1);
                MMA16816(acc[nt], ah0,ah1,ah2,ah3, bl0,bl1);
                MMA16816(acc[nt], al0,al1,al2,al3, bh0,bh1);
            }
        }

        float* out = isV ? g_vals : g_keys;
        #pragma unroll
        for (int nt = 0; nt < 8; nt++){
            const int col = colb + 8*nt + cc;
            const float b0 = bias[isV*128 + col];
            const float b1 = bias[isV*128 + col + 1];
            float2 v0; v0.x = acc[nt][0] + b0; v0.y = acc[nt][1] + b1;
            float2 v1; v1.x = acc[nt][2] + b0; v1.y = acc[nt][3] + b1;
            *(float2*)&out[gb + (size_t)r0*128 + col]       = v0;
            *(float2*)&out[gb + (size_t)(r0+8)*128 + col]   = v1;
        }
    }
}

// ---------------- kernel 2: slot LN + q projection ----------------
__global__ __launch_bounds__(128) void slot_q_kernel(
    const float* __restrict__ Wq, const float* __restrict__ bq,
    const float* __restrict__ gs, const float* __restrict__ bs)
{
    __shared__ float sn[128];
    __shared__ float red[8];
    const int row = blockIdx.x, tid = threadIdx.x;
    const int lane = tid & 31, wid = tid >> 5;
    float v = g_slots[row*128 + tid];
    float s = v, ss = v*v;
    #pragma unroll
    for (int o = 16; o; o >>= 1){
        s  += __shfl_xor_sync(0xffffffffu, s, o);
        ss += __shfl_xor_sync(0xffffffffu, ss, o);
    }
    if (lane == 0){ red[wid] = s; red[4+wid] = ss; }
    __syncthreads();
    s  = red[0]+red[1]+red[2]+red[3];
    ss = red[4]+red[5]+red[6]+red[7];
    float m = s*(1.f/128.f);
    float rstd = rsqrtf(ss*(1.f/128.f) - m*m + 1e-5f);
    sn[tid] = (v - m)*rstd*gs[tid] + bs[tid];
    g_upd[row*128 + tid] = 0.f;
    if (tid == 0) g_rs[row] = 0.f;
    __syncthreads();
    float acc = bq[tid];
    const float4* wr  = (const float4*)(Wq + tid*128);
    const float4* sn4 = (const float4*)sn;
    #pragma unroll
    for (int e = 0; e < 32; e++){
        float4 w = wr[e], q = sn4[e];
        acc += w.x*q.x + w.y*q.y + w.z*q.z + w.w*q.w;
    }
    g_q[row*128 + tid] = acc * SCALE;
}

// ---------------- kernel 3: logits + softmax over slots ----------------
__global__ __launch_bounds__(128) void attn_kernel()
{
    __shared__ float qs[NS*DD];
    __shared__ float srs[NS];
    const int tid = threadIdx.x;
    const int bb = blockIdx.x >> 5;
    const int n0 = (blockIdx.x & 31) * 128;
    #pragma unroll
    for (int r = 0; r < 8; r++) qs[r*128 + tid] = g_q[bb*1024 + r*128 + tid];
    if (tid < 8) srs[tid] = 0.f;
    __syncthreads();

    float l[8];
    #pragma unroll
    for (int i = 0; i < 8; i++) l[i] = 0.f;
    const float4* krow = (const float4*)(g_keys + (size_t)(bb*4096 + n0 + tid)*128);
    const float4* q4 = (const float4*)qs;
    #pragma unroll 8
    for (int e = 0; e < 32; e++){
        float4 kv = krow[e];
        #pragma unroll
        for (int i = 0; i < 8; i++){
            float4 qv = q4[i*32 + e];
            l[i] += kv.x*qv.x + kv.y*qv.y + kv.z*qv.z + kv.w*qv.w;
        }
    }
    float mx = l[0];
    #pragma unroll
    for (int i = 1; i < 8; i++) mx = fmaxf(mx, l[i]);
    float sum = 0.f;
    #pragma unroll
    for (int i = 0; i < 8; i++){ l[i] = __expf(l[i]-mx); sum += l[i]; }
    float inv = 1.f/sum;
    const int base = bb*NS*NN + n0 + tid;
    #pragma unroll
    for (int i = 0; i < 8; i++){
        float p = l[i]*inv + 1e-8f;
        g_attn[base + i*NN] = p;
        l[i] = p;
    }
    #pragma unroll
    for (int i = 0; i < 8; i++){
        float r = l[i];
        #pragma unroll
        for (int o = 16; o; o >>= 1) r += __shfl_xor_sync(0xffffffffu, r, o);
        if ((tid & 31) == 0) atomicAdd(&srs[i], r);
    }
    __syncthreads();
    if (tid < 8) atomicAdd(&g_rs[bb*8 + tid], srs[tid]);
}

// ---------------- kernel 4: updates = (attn @ V) / rowsum ----------------
__global__ __launch_bounds__(128) void upd_kernel()
{
    __shared__ float att_s[8][256];
    __shared__ float rsv[8];
    const int tid = threadIdx.x;
    const int bb = blockIdx.x >> 4;
    const int n0 = (blockIdx.x & 15) * 256;
    #pragma unroll
    for (int i = 0; i < 8; i++){
        att_s[i][tid]     = g_attn[bb*NS*NN + i*NN + n0 + tid];
        att_s[i][tid+128] = g_attn[bb*NS*NN + i*NN + n0 + tid + 128];
    }
    if (tid < 8) rsv[tid] = g_rs[bb*8 + tid];
    __syncthreads();
    float acc[8];
    #pragma unroll
    for (int i = 0; i < 8; i++) acc[i] = 0.f;
    const float* vp = g_vals + (size_t)(bb*4096 + n0)*128 + tid;
    #pragma unroll 2
    for (int n = 0; n < 256; n += 4){
        float v0 = vp[(n+0)*128];
        float v1 = vp[(n+1)*128];
        float v2 = vp[(n+2)*128];
        float v3 = vp[(n+3)*128];
        #pragma unroll
        for (int i = 0; i < 8; i++){
            const float4 a = *(const float4*)&att_s[i][n];
            acc[i] += a.x*v0 + a.y*v1 + a.z*v2 + a.w*v3;
        }
    }
    #pragma unroll
    for (int i = 0; i < 8; i++)
        atomicAdd(&g_upd[(bb*8+i)*128 + tid], acc[i] / rsv[i]);
}

// ---------------- kernel 5: GRU cell + LN + MLP residual ----------------
__global__ __launch_bounds__(128) void gru_mlp_kernel(
    const float* __restrict__ W_ih, const float* __restrict__ W_hh,
    const float* __restrict__ b_ih, const float* __restrict__ b_hh,
    const float* __restrict__ gm, const float* __restrict__ bm,
    const float* __restrict__ W1, const float* __restrict__ b1,
    const float* __restrict__ W2, const float* __restrict__ b2)
{
    __shared__ float us[128], ps[128], hs[128], red[8];
    const int b = blockIdx.x, tid = threadIdx.x;
    const int lane = tid & 31, wid = tid >> 5;
    for (int slot = 0; slot < 8; slot++){
        const int row = b*8 + slot;
        float u = g_upd[row*128 + tid];
        float h = g_slots[row*128 + tid];
        us[tid] = u; ps[tid] = h;
        __syncthreads();
        float gi[3], gh[3];
        #pragma unroll
        for (int g = 0; g < 3; g++){
            const float4* wi = (const float4*)(W_ih + (g*128 + tid)*128);
            const float4* wh = (const float4*)(W_hh + (g*128 + tid)*128);
            float ai = b_ih[g*128 + tid];
            float ah = b_hh[g*128 + tid];
            const float4* u4 = (const float4*)us;
            const float4* p4 = (const float4*)ps;
            #pragma unroll 8
            for (int e = 0; e < 32; e++){
                float4 a = wi[e], uu = u4[e];
                ai += a.x*uu.x + a.y*uu.y + a.z*uu.z + a.w*uu.w;
                float4 c = wh[e], pp = p4[e];
                ah += c.x*pp.x + c.y*pp.y + c.z*pp.z + c.w*pp.w;
            }
            gi[g] = ai; gh[g] = ah;
        }
        float r = 1.f/(1.f + __expf(-(gi[0]+gh[0])));
        float z = 1.f/(1.f + __expf(-(gi[1]+gh[1])));
        float n = tanhf(gi[2] + r*gh[2]);
        float hn = (1.f - z)*n + z*h;
        float s = hn, ss = hn*hn;
        #pragma unroll
        for (int o = 16; o; o >>= 1){
            s  += __shfl_xor_sync(0xffffffffu, s, o);
            ss += __shfl_xor_sync(0xffffffffu, ss, o);
        }
        if (lane == 0){ red[wid] = s; red[4+wid] = ss; }
        __syncthreads();
        s  = red[0]+red[1]+red[2]+red[3];
        ss = red[4]+red[5]+red[6]+red[7];
        float m = s*(1.f/128.f);
        float rstd = rsqrtf(ss*(1.f/128.f) - m*m + 1e-5f);
        hs[tid] = (hn - m)*rstd*gm[tid] + bm[tid];
        __syncthreads();
        float hid = b1[tid];
        {
            const float4* w  = (const float4*)(W1 + tid*128);
            const float4* h4 = (const float4*)hs;
            #pragma unroll 8
            for (int e = 0; e < 32; e++){
                float4 a = w[e], xx = h4[e];
                hid += a.x*xx.x + a.y*xx.y + a.z*xx.z + a.w*xx.w;
            }
        }
        hid = fmaxf(hid, 0.f);
        us[tid] = hid;
        __syncthreads();
        float out = hn + b2[tid];
        {
            const float4* w  = (const float4*)(W2 + tid*128);
            const float4* h4 = (const float4*)us;
            #pragma unroll 8
            for (int e = 0; e < 32; e++){
                float4 a = w[e], xx = h4[e];
                out += a.x*xx.x + a.y*xx.y + a.z*xx.z + a.w*xx.w;
            }
        }
        g_slots[row*128 + tid] = out;
        __syncthreads();
    }
}

// ---------------- launch ----------------
extern "C" void kernel_launch(void* const* d_in, const int* in_sizes, int n_in,
                              void* d_out, int out_size)
{
    const float* x    = (const float*)d_in[0];
    const float* si   = (const float*)d_in[1];
    const float* Wq   = (const float*)d_in[2];
    const float* bq   = (const float*)d_in[3];
    const float* Wk   = (const float*)d_in[4];
    const float* bk   = (const float*)d_in[5];
    const float* Wv   = (const float*)d_in[6];
    const float* bv   = (const float*)d_in[7];
    const float* gin  = (const float*)d_in[8];
    const float* bin  = (const float*)d_in[9];
    const float* gsl  = (const float*)d_in[10];
    const float* bsl  = (const float*)d_in[11];
    const float* gm   = (const float*)d_in[12];
    const float* bm   = (const float*)d_in[13];
    const float* W1   = (const float*)d_in[14];
    const float* b1   = (const float*)d_in[15];
    const float* W2   = (const float*)d_in[16];
    const float* b2   = (const float*)d_in[17];
    const float* W_ih = (const float*)d_in[18];
    const float* W_hh = (const float*)d_in[19];
    const float* b_ih = (const float*)d_in[20];
    const float* b_hh = (const float*)d_in[21];

    static bool attr_set = false;
    if (!attr_set){
        cudaFuncSetAttribute(ln_kv_mma_kernel,
                             cudaFuncAttributeMaxDynamicSharedMemorySize, S_TOTAL);
        attr_set = true;
    }

    init_slots_kernel<<<256, 256>>>(si);
    prep_w_kernel<<<128, 256>>>(Wk, Wv);
    ln_kv_mma_kernel<<<2048, 256, S_TOTAL>>>(x, bk, bv, gin, bin);
    for (int it = 0; it < 3; it++){
        slot_q_kernel<<<512, 128>>>(Wq, bq, gsl, bsl);
        attn_kernel<<<2048, 128>>>();
        upd_kernel<<<1024, 128>>>();
        gru_mlp_kernel<<<64, 128>>>(W_ih, W_hh, b_ih, b_hh, gm, bm, W1, b1, W2, b2);
    }
    export_kernel<<<256, 256>>>((float*)d_out);
}

// round 4
// speedup vs baseline: 1.8418x; 1.4109x over previous
#include <cuda_runtime.h>
#include <cuda_bf16.h>
#include <cstdint>

#define BB 64
#define NN 4096
#define DD 128
#define NS 8
#define SCALE 0.08838834764831845f

// ---------------- device scratch ----------------
__device__ float g_keys[BB*NN*DD];   // 134 MB
__device__ float g_vals[BB*NN*DD];   // 134 MB
__device__ float g_q[BB*NS*DD];
__device__ float g_slots[BB*NS*DD];
__device__ float g_upd[BB*NS*DD];    // UNNORMALIZED update accumulators
__device__ float g_rs[BB*NS];        // rowsum accumulators
// bf16 hi/lo images of [Wk;Wv], pitched rows of 136 elems (272B)
#define WPITCH 136
#define WIMG   (128*WPITCH)
__device__ __nv_bfloat16 g_w_hi[2*WIMG];
__device__ __nv_bfloat16 g_w_lo[2*WIMG];

__device__ __forceinline__ uint32_t smem_u32(const void* p){
    uint32_t a;
    asm("{ .reg .u64 t; cvta.to.shared.u64 t, %1; cvt.u32.u64 %0, t; }" : "=r"(a) : "l"(p));
    return a;
}

#define LDSM4(r0,r1,r2,r3,addr) \
    asm volatile("ldmatrix.sync.aligned.m8n8.x4.shared.b16 {%0,%1,%2,%3}, [%4];" \
        : "=r"(r0),"=r"(r1),"=r"(r2),"=r"(r3) : "r"(addr))
#define MMA16816(c,a0,a1,a2,a3,b0,b1) \
    asm volatile("mma.sync.aligned.m16n8k16.row.col.f32.bf16.bf16.f32 " \
        "{%0,%1,%2,%3}, {%4,%5,%6,%7}, {%8,%9}, {%0,%1,%2,%3};" \
        : "+f"((c)[0]),"+f"((c)[1]),"+f"((c)[2]),"+f"((c)[3]) \
        : "r"(a0),"r"(a1),"r"(a2),"r"(a3),"r"(b0),"r"(b1))

// SMEM layout (dynamic):
#define S_BIAS  0                        // 256 floats (bk | bv)
#define S_A_HI  1024
#define S_A_LO  (1024 + 34816)
#define S_W     (1024 + 2*34816)         // KH, KL, VH, VL, each 34816 B
#define S_TOTAL (S_W + 4*34816)          // 209920 B
#define APITCHB 272

__global__ __launch_bounds__(256) void export_kernel(float* __restrict__ dst){
    int i = blockIdx.x*256 + threadIdx.x;
    dst[i] = g_slots[i];
}

// ---------------- prep: Wk/Wv -> pitched bf16 hi/lo images ----------------
__global__ __launch_bounds__(256) void prep_w_kernel(const float* __restrict__ Wk,
                                                     const float* __restrict__ Wv){
    int i = blockIdx.x*256 + threadIdx.x;
    int m = i >> 14;
    int idx = i & 16383;
    int row = idx >> 7, k = idx & 127;
    float v = (m ? Wv : Wk)[row*128 + k];
    __nv_bfloat16 h = __float2bfloat16_rn(v);
    __nv_bfloat16 l = __float2bfloat16_rn(v - __bfloat162float(h));
    g_w_hi[m*WIMG + row*WPITCH + k] = h;
    g_w_lo[m*WIMG + row*WPITCH + k] = l;
}

// ---------------- kernel 1: LN(x) + K/V projection, 2 tiles per CTA ----------------
// grid 1024, 256 threads (8 warps), 256 rows of x per CTA
__global__ __launch_bounds__(256, 1) void ln_kv_mma_kernel(
    const float* __restrict__ x,
    const float* __restrict__ bk, const float* __restrict__ bv,
    const float* __restrict__ gin, const float* __restrict__ bin)
{
    extern __shared__ __align__(1024) char smem[];
    const uint32_t sb = smem_u32(smem);
    const int tid = threadIdx.x;
    const int wid = tid >> 5, lane = tid & 31;

    if (tid < 128){
        ((float*)(smem + S_BIAS))[tid]       = bk[tid];
        ((float*)(smem + S_BIAS))[tid + 128] = bv[tid];
    }
    // ---- copy weight images once: KH, KL, VH, VL ----
    {
        uint4* dst = (uint4*)(smem + S_W);
        const uint4* hi4 = (const uint4*)g_w_hi;
        const uint4* lo4 = (const uint4*)g_w_lo;
        for (int i = tid; i < 2176; i += 256){
            dst[i]        = hi4[i];
            dst[2176 + i] = lo4[i];
            dst[4352 + i] = hi4[2176 + i];
            dst[6528 + i] = lo4[2176 + i];
        }
    }

    // per-lane ldmatrix address components
    const int aRow  = (lane & 7) + ((lane >> 3) & 1) * 8;
    const int aKoff = (lane >> 4) * 16;
    const uint32_t aHiBase = sb + S_A_HI + (16*wid + aRow)*APITCHB + aKoff;
    const uint32_t aLoBase = sb + S_A_LO + (16*wid + aRow)*APITCHB + aKoff;
    // B x4: two n-tiles at once: lanes 0-7: nt k0, 8-15: nt k1, 16-23: nt+1 k0, 24-31: nt+1 k1
    const int bRow4 = (lane & 7) + ((lane >> 4) & 1) * 8;
    const int bK4   = ((lane >> 3) & 1) * 16;
    const float* bias = (const float*)(smem + S_BIAS);
    const int r0 = 16*wid + (lane >> 2);
    const int cc = 2*(lane & 3);

    #pragma unroll 1
    for (int t = 0; t < 2; t++){
        __syncthreads();   // weights ready (t=0) / prior MMA reads done (t=1)

        // ---- LayerNorm: 2 threads per row, 64 cols each ----
        {
            const int row = tid >> 1, half = tid & 1;
            const float* xr = x + ((size_t)(blockIdx.x*256 + t*128 + row))*128 + half*64;
            float4 v[16];
            float s = 0.f, ss = 0.f;
            #pragma unroll
            for (int j = 0; j < 16; j++){
                v[j] = ((const float4*)xr)[j];
                s  += v[j].x + v[j].y + v[j].z + v[j].w;
                ss += v[j].x*v[j].x + v[j].y*v[j].y + v[j].z*v[j].z + v[j].w*v[j].w;
            }
            s  += __shfl_xor_sync(0xffffffffu, s, 1);
            ss += __shfl_xor_sync(0xffffffffu, ss, 1);
            const float m = s * (1.f/128.f);
            const float rstd = rsqrtf(ss*(1.f/128.f) - m*m + 1e-5f);
            #pragma unroll
            for (int j = 0; j < 16; j++){
                const int k0 = half*64 + j*4;
                float4 g4 = ((const float4*)gin)[k0>>2];
                float4 b4 = ((const float4*)bin)[k0>>2];
                float n0 = (v[j].x - m)*rstd*g4.x + b4.x;
                float n1 = (v[j].y - m)*rstd*g4.y + b4.y;
                float n2 = (v[j].z - m)*rstd*g4.z + b4.z;
                float n3 = (v[j].w - m)*rstd*g4.w + b4.w;
                __nv_bfloat16 h0 = __float2bfloat16_rn(n0), h1 = __float2bfloat16_rn(n1);
                __nv_bfloat16 h2 = __float2bfloat16_rn(n2), h3 = __float2bfloat16_rn(n3);
                __nv_bfloat162 hA; hA.x = h0; hA.y = h1;
                __nv_bfloat162 hB; hB.x = h2; hB.y = h3;
                __nv_bfloat162 lA, lB;
                lA.x = __float2bfloat16_rn(n0 - __bfloat162float(h0));
                lA.y = __float2bfloat16_rn(n1 - __bfloat162float(h1));
                lB.x = __float2bfloat16_rn(n2 - __bfloat162float(h2));
                lB.y = __float2bfloat16_rn(n3 - __bfloat162float(h3));
                char* ahp = smem + S_A_HI + row*APITCHB + k0*2;
                char* alp = smem + S_A_LO + row*APITCHB + k0*2;
                *(__nv_bfloat162*)(ahp)     = hA;
                *(__nv_bfloat162*)(ahp + 4) = hB;
                *(__nv_bfloat162*)(alp)     = lA;
                *(__nv_bfloat162*)(alp + 4) = lB;
            }
        }
        __syncthreads();

        const size_t gb = (size_t)blockIdx.x * 32768 + (size_t)t * 16384;

        #pragma unroll 1
        for (int p = 0; p < 4; p++){
            const int isV  = p >> 1;
            const int colb = (p & 1) * 64;
            const uint32_t wHiBase = sb + S_W + isV*69632 + (colb + bRow4)*APITCHB + bK4;
            const uint32_t wLoBase = wHiBase + 34816;

            float acc[8][4];
            #pragma unroll
            for (int nt = 0; nt < 8; nt++){
                acc[nt][0]=0.f; acc[nt][1]=0.f; acc[nt][2]=0.f; acc[nt][3]=0.f;
            }

            #pragma unroll
            for (int kc = 0; kc < 8; kc++){
                const uint32_t ko = kc*32;
                uint32_t ah0,ah1,ah2,ah3, al0,al1,al2,al3;
                LDSM4(ah0,ah1,ah2,ah3, aHiBase + ko);
                LDSM4(al0,al1,al2,al3, aLoBase + ko);
                #pragma unroll
                for (int ntp = 0; ntp < 4; ntp++){
                    uint32_t bh0,bh1,bh2,bh3, bl0,bl1,bl2,bl3;
                    LDSM4(bh0,bh1,bh2,bh3, wHiBase + ntp*(16*APITCHB) + ko);
                    LDSM4(bl0,bl1,bl2,bl3, wLoBase + ntp*(16*APITCHB) + ko);
                    MMA16816(acc[2*ntp],   ah0,ah1,ah2,ah3, bh0,bh1);
                    MMA16816(acc[2*ntp],   ah0,ah1,ah2,ah3, bl0,bl1);
                    MMA16816(acc[2*ntp],   al0,al1,al2,al3, bh0,bh1);
                    MMA16816(acc[2*ntp+1], ah0,ah1,ah2,ah3, bh2,bh3);
                    MMA16816(acc[2*ntp+1], ah0,ah1,ah2,ah3, bl2,bl3);
                    MMA16816(acc[2*ntp+1], al0,al1,al2,al3, bh2,bh3);
                }
            }

            float* out = isV ? g_vals : g_keys;
            #pragma unroll
            for (int nt = 0; nt < 8; nt++){
                const int col = colb + 8*nt + cc;
                const float b0 = bias[isV*128 + col];
                const float b1 = bias[isV*128 + col + 1];
                float2 v0; v0.x = acc[nt][0] + b0; v0.y = acc[nt][1] + b1;
                float2 v1; v1.x = acc[nt][2] + b0; v1.y = acc[nt][3] + b1;
                *(float2*)&out[gb + (size_t)r0*128 + col]       = v0;
                *(float2*)&out[gb + (size_t)(r0+8)*128 + col]   = v1;
            }
        }
    }
}

// ---------------- init: slots <- slots_init, q0, zero accumulators ----------------
// grid 512 (one row), 128 threads
__global__ __launch_bounds__(128) void init_q_kernel(
    const float* __restrict__ si,
    const float* __restrict__ Wq, const float* __restrict__ bq,
    const float* __restrict__ gs, const float* __restrict__ bs)
{
    __shared__ float sn[128];
    __shared__ float red[8];
    const int row = blockIdx.x, tid = threadIdx.x;
    const int lane = tid & 31, wrp = tid >> 5;
    float v = si[row*128 + tid];
    g_slots[row*128 + tid] = v;
    g_upd[row*128 + tid] = 0.f;
    if (tid == 0) g_rs[row] = 0.f;
    float s = v, ss = v*v;
    #pragma unroll
    for (int o = 16; o; o >>= 1){
        s  += __shfl_xor_sync(0xffffffffu, s, o);
        ss += __shfl_xor_sync(0xffffffffu, ss, o);
    }
    if (lane == 0){ red[wrp] = s; red[4+wrp] = ss; }
    __syncthreads();
    s  = red[0]+red[1]+red[2]+red[3];
    ss = red[4]+red[5]+red[6]+red[7];
    float m = s*(1.f/128.f);
    float rstd = rsqrtf(ss*(1.f/128.f) - m*m + 1e-5f);
    sn[tid] = (v - m)*rstd*gs[tid] + bs[tid];
    __syncthreads();
    float acc = bq[tid];
    const float4* wr  = (const float4*)(Wq + tid*128);
    const float4* sn4 = (const float4*)sn;
    #pragma unroll
    for (int e = 0; e < 32; e++){
        float4 w = wr[e], q = sn4[e];
        acc += w.x*q.x + w.y*q.y + w.z*q.z + w.w*q.w;
    }
    g_q[row*128 + tid] = acc * SCALE;
}

// ---------------- kernel 3: FUSED logits + softmax + (attn @ V) partials ----------------
// one thread per token; 128 tokens per block; grid = B * 32
__global__ __launch_bounds__(128) void fused_attn_upd_kernel()
{
    __shared__ float qs[NS*DD];
    __shared__ float ps[NS][128];
    __shared__ float srs[NS];
    const int tid = threadIdx.x;
    const int bb = blockIdx.x >> 5;
    const int n0 = (blockIdx.x & 31) * 128;
    #pragma unroll
    for (int r = 0; r < 8; r++) qs[r*128 + tid] = g_q[bb*1024 + r*128 + tid];
    if (tid < 8) srs[tid] = 0.f;
    __syncthreads();

    // ---- phase 1: logits + softmax over slots ----
    float l[8];
    #pragma unroll
    for (int i = 0; i < 8; i++) l[i] = 0.f;
    const float4* krow = (const float4*)(g_keys + (size_t)(bb*4096 + n0 + tid)*128);
    const float4* q4 = (const float4*)qs;
    #pragma unroll 8
    for (int e = 0; e < 32; e++){
        float4 kv = krow[e];
        #pragma unroll
        for (int i = 0; i < 8; i++){
            float4 qv = q4[i*32 + e];
            l[i] += kv.x*qv.x + kv.y*qv.y + kv.z*qv.z + kv.w*qv.w;
        }
    }
    float mx = l[0];
    #pragma unroll
    for (int i = 1; i < 8; i++) mx = fmaxf(mx, l[i]);
    float sum = 0.f;
    #pragma unroll
    for (int i = 0; i < 8; i++){ l[i] = __expf(l[i]-mx); sum += l[i]; }
    float inv = 1.f/sum;
    #pragma unroll
    for (int i = 0; i < 8; i++){
        float p = l[i]*inv + 1e-8f;
        ps[i][tid] = p;
        l[i] = p;
    }
    #pragma unroll
    for (int i = 0; i < 8; i++){
        float r = l[i];
        #pragma unroll
        for (int o = 16; o; o >>= 1) r += __shfl_xor_sync(0xffffffffu, r, o);
        if ((tid & 31) == 0) atomicAdd(&srs[i], r);
    }
    __syncthreads();

    // ---- phase 2: partial updates = p^T @ V over this token chunk ----
    float acc[8];
    #pragma unroll
    for (int i = 0; i < 8; i++) acc[i] = 0.f;
    const float* vp = g_vals + (size_t)(bb*4096 + n0)*128 + tid;
    #pragma unroll 4
    for (int n = 0; n < 128; n += 4){
        float v0 = vp[(n+0)*128];
        float v1 = vp[(n+1)*128];
        float v2 = vp[(n+2)*128];
        float v3 = vp[(n+3)*128];
        #pragma unroll
        for (int i = 0; i < 8; i++){
            const float4 a = *(const float4*)&ps[i][n];   // broadcast
            acc[i] += a.x*v0 + a.y*v1 + a.z*v2 + a.w*v3;
        }
    }
    #pragma unroll
    for (int i = 0; i < 8; i++)
        atomicAdd(&g_upd[(bb*8+i)*128 + tid], acc[i]);
    if (tid < 8) atomicAdd(&g_rs[bb*8 + tid], srs[tid]);
}

// ---------------- kernel 4: GRU + LN + MLP + next-iter q, one row per block ----------------
__global__ __launch_bounds__(128) void gru_mlp_q_kernel(
    const float* __restrict__ W_ih, const float* __restrict__ W_hh,
    const float* __restrict__ b_ih, const float* __restrict__ b_hh,
    const float* __restrict__ gm, const float* __restrict__ bm,
    const float* __restrict__ W1, const float* __restrict__ b1,
    const float* __restrict__ W2, const float* __restrict__ b2,
    const float* __restrict__ Wq, const float* __restrict__ bq,
    const float* __restrict__ gs, const float* __restrict__ bs)
{
    __shared__ float us[128], ps_[128], hs[128], red[8];
    const int row = blockIdx.x, tid = threadIdx.x;
    const int lane = tid & 31, wrp = tid >> 5;

    const float rs = g_rs[row];
    float u = g_upd[row*128 + tid] / rs;
    float h = g_slots[row*128 + tid];
    // re-zero accumulators for next iteration
    g_upd[row*128 + tid] = 0.f;
    if (tid == 0) g_rs[row] = 0.f;
    us[tid] = u; ps_[tid] = h;
    __syncthreads();

    float gi[3], gh[3];
    #pragma unroll
    for (int g = 0; g < 3; g++){
        const float4* wi = (const float4*)(W_ih + (g*128 + tid)*128);
        const float4* wh = (const float4*)(W_hh + (g*128 + tid)*128);
        float ai = b_ih[g*128 + tid];
        float ah = b_hh[g*128 + tid];
        const float4* u4 = (const float4*)us;
        const float4* p4 = (const float4*)ps_;
        #pragma unroll 8
        for (int e = 0; e < 32; e++){
            float4 a = wi[e], uu = u4[e];
            ai += a.x*uu.x + a.y*uu.y + a.z*uu.z + a.w*uu.w;
            float4 c = wh[e], pp = p4[e];
            ah += c.x*pp.x + c.y*pp.y + c.z*pp.z + c.w*pp.w;
        }
        gi[g] = ai; gh[g] = ah;
    }
    float r = 1.f/(1.f + __expf(-(gi[0]+gh[0])));
    float z = 1.f/(1.f + __expf(-(gi[1]+gh[1])));
    float n = tanhf(gi[2] + r*gh[2]);
    float hn = (1.f - z)*n + z*h;

    // LayerNorm(hn) for MLP
    float s = hn, ss = hn*hn;
    #pragma unroll
    for (int o = 16; o; o >>= 1){
        s  += __shfl_xor_sync(0xffffffffu, s, o);
        ss += __shfl_xor_sync(0xffffffffu, ss, o);
    }
    if (lane == 0){ red[wrp] = s; red[4+wrp] = ss; }
    __syncthreads();
    s  = red[0]+red[1]+red[2]+red[3];
    ss = red[4]+red[5]+red[6]+red[7];
    float m = s*(1.f/128.f);
    float rstd = rsqrtf(ss*(1.f/128.f) - m*m + 1e-5f);
    hs[tid] = (hn - m)*rstd*gm[tid] + bm[tid];
    __syncthreads();

    float hid = b1[tid];
    {
        const float4* w  = (const float4*)(W1 + tid*128);
        const float4* h4 = (const float4*)hs;
        #pragma unroll 8
        for (int e = 0; e < 32; e++){
            float4 a = w[e], xx = h4[e];
            hid += a.x*xx.x + a.y*xx.y + a.z*xx.z + a.w*xx.w;
        }
    }
    hid = fmaxf(hid, 0.f);
    us[tid] = hid;
    __syncthreads();
    float out = hn + b2[tid];
    {
        const float4* w  = (const float4*)(W2 + tid*128);
        const float4* h4 = (const float4*)us;
        #pragma unroll 8
        for (int e = 0; e < 32; e++){
            float4 a = w[e], xx = h4[e];
            out += a.x*xx.x + a.y*xx.y + a.z*xx.z + a.w*xx.w;
        }
    }
    g_slots[row*128 + tid] = out;

    // ---- next-iteration q = LN(out)*g+b @ Wq^T * SCALE ----
    float s2 = out, ss2 = out*out;
    #pragma unroll
    for (int o = 16; o; o >>= 1){
        s2  += __shfl_xor_sync(0xffffffffu, s2, o);
        ss2 += __shfl_xor_sync(0xffffffffu, ss2, o);
    }
    __syncthreads();        // red[] reuse safe
    if (lane == 0){ red[wrp] = s2; red[4+wrp] = ss2; }
    __syncthreads();
    s2  = red[0]+red[1]+red[2]+red[3];
    ss2 = red[4]+red[5]+red[6]+red[7];
    float m2 = s2*(1.f/128.f);
    float rstd2 = rsqrtf(ss2*(1.f/128.f) - m2*m2 + 1e-5f);
    ps_[tid] = (out - m2)*rstd2*gs[tid] + bs[tid];
    __syncthreads();
    float qa = bq[tid];
    {
        const float4* w  = (const float4*)(Wq + tid*128);
        const float4* s4 = (const float4*)ps_;
        #pragma unroll 8
        for (int e = 0; e < 32; e++){
            float4 a = w[e], xx = s4[e];
            qa += a.x*xx.x + a.y*xx.y + a.z*xx.z + a.w*xx.w;
        }
    }
    g_q[row*128 + tid] = qa * SCALE;
}

// ---------------- launch ----------------
extern "C" void kernel_launch(void* const* d_in, const int* in_sizes, int n_in,
                              void* d_out, int out_size)
{
    const float* x    = (const float*)d_in[0];
    const float* si   = (const float*)d_in[1];
    const float* Wq   = (const float*)d_in[2];
    const float* bq   = (const float*)d_in[3];
    const float* Wk   = (const float*)d_in[4];
    const float* bk   = (const float*)d_in[5];
    const float* Wv   = (const float*)d_in[6];
    const float* bv   = (const float*)d_in[7];
    const float* gin  = (const float*)d_in[8];
    const float* bin  = (const float*)d_in[9];
    const float* gsl  = (const float*)d_in[10];
    const float* bsl  = (const float*)d_in[11];
    const float* gm   = (const float*)d_in[12];
    const float* bm   = (const float*)d_in[13];
    const float* W1   = (const float*)d_in[14];
    const float* b1   = (const float*)d_in[15];
    const float* W2   = (const float*)d_in[16];
    const float* b2   = (const float*)d_in[17];
    const float* W_ih = (const float*)d_in[18];
    const float* W_hh = (const float*)d_in[19];
    const float* b_ih = (const float*)d_in[20];
    const float* b_hh = (const float*)d_in[21];

    static bool attr_set = false;
    if (!attr_set){
        cudaFuncSetAttribute(ln_kv_mma_kernel,
                             cudaFuncAttributeMaxDynamicSharedMemorySize, S_TOTAL);
        attr_set = true;
    }

    prep_w_kernel<<<128, 256>>>(Wk, Wv);
    init_q_kernel<<<512, 128>>>(si, Wq, bq, gsl, bsl);
    ln_kv_mma_kernel<<<1024, 256, S_TOTAL>>>(x, bk, bv, gin, bin);
    for (int it = 0; it < 3; it++){
        fused_attn_upd_kernel<<<2048, 128>>>();
        gru_mlp_q_kernel<<<512, 128>>>(W_ih, W_hh, b_ih, b_hh, gm, bm,
                                       W1, b1, W2, b2, Wq, bq, gsl, bsl);
    }
    export_kernel<<<256, 256>>>((float*)d_out);
}

// round 6
// speedup vs baseline: 2.3717x; 1.2877x over previous
#include <cuda_runtime.h>
#include <cuda_bf16.h>
#include <cstdint>

#define BB 64
#define NN 4096
#define DD 128
#define NS 8
#define SCALE 0.08838834764831845f

// ---------------- device scratch ----------------
__device__ float g_keys[BB*NN*DD];
__device__ float g_vals[BB*NN*DD];
__device__ float g_q[BB*NS*DD];
__device__ float g_slots[BB*NS*DD];
__device__ float g_upd[BB*NS*DD];    // UNNORMALIZED update accumulators
__device__ float g_rs[BB*NS];        // rowsum accumulators
#define WPITCH 136
#define WIMG   (128*WPITCH)
__device__ __nv_bfloat16 g_w_hi[2*WIMG];
__device__ __nv_bfloat16 g_w_lo[2*WIMG];

__device__ __forceinline__ uint32_t smem_u32(const void* p){
    uint32_t a;
    asm("{ .reg .u64 t; cvta.to.shared.u64 t, %1; cvt.u32.u64 %0, t; }" : "=r"(a) : "l"(p));
    return a;
}

#define LDSM4(r0,r1,r2,r3,addr) \
    asm volatile("ldmatrix.sync.aligned.m8n8.x4.shared.b16 {%0,%1,%2,%3}, [%4];" \
        : "=r"(r0),"=r"(r1),"=r"(r2),"=r"(r3) : "r"(addr))
#define MMA16816(c,a0,a1,a2,a3,b0,b1) \
    asm volatile("mma.sync.aligned.m16n8k16.row.col.f32.bf16.bf16.f32 " \
        "{%0,%1,%2,%3}, {%4,%5,%6,%7}, {%8,%9}, {%0,%1,%2,%3};" \
        : "+f"((c)[0]),"+f"((c)[1]),"+f"((c)[2]),"+f"((c)[3]) \
        : "r"(a0),"r"(a1),"r"(a2),"r"(a3),"r"(b0),"r"(b1))

#define S_BIAS  0
#define S_A_HI  1024
#define S_A_LO  (1024 + 34816)
#define S_W     (1024 + 2*34816)         // KH, KL, VH, VL
#define S_TOTAL (S_W + 4*34816)
#define APITCHB 272

__global__ __launch_bounds__(256) void export_kernel(float* __restrict__ dst){
    int i = blockIdx.x*256 + threadIdx.x;
    dst[i] = g_slots[i];
}

// ---------------- prep: Wk/Wv -> pitched bf16 hi/lo images ----------------
__global__ __launch_bounds__(256) void prep_w_kernel(const float* __restrict__ Wk,
                                                     const float* __restrict__ Wv){
    int i = blockIdx.x*256 + threadIdx.x;
    int m = i >> 14;
    int idx = i & 16383;
    int row = idx >> 7, k = idx & 127;
    float v = (m ? Wv : Wk)[row*128 + k];
    __nv_bfloat16 h = __float2bfloat16_rn(v);
    __nv_bfloat16 l = __float2bfloat16_rn(v - __bfloat162float(h));
    g_w_hi[m*WIMG + row*WPITCH + k] = h;
    g_w_lo[m*WIMG + row*WPITCH + k] = l;
}

// ---------------- kernel 1: LN(x) + K/V projection via mma.sync bf16x3 ----------------
// grid 1024, 256 threads (8 warps), 256 rows of x per CTA
__global__ __launch_bounds__(256, 1) void ln_kv_mma_kernel(
    const float* __restrict__ x,
    const float* __restrict__ bk, const float* __restrict__ bv,
    const float* __restrict__ gin, const float* __restrict__ bin)
{
    extern __shared__ __align__(1024) char smem[];
    const uint32_t sb = smem_u32(smem);
    const int tid = threadIdx.x;
    const int wid = tid >> 5, lane = tid & 31;

    if (tid < 128){
        ((float*)(smem + S_BIAS))[tid]       = bk[tid];
        ((float*)(smem + S_BIAS))[tid + 128] = bv[tid];
    }
    {
        uint4* dst = (uint4*)(smem + S_W);
        const uint4* hi4 = (const uint4*)g_w_hi;
        const uint4* lo4 = (const uint4*)g_w_lo;
        for (int i = tid; i < 2176; i += 256){
            dst[i]        = hi4[i];
            dst[2176 + i] = lo4[i];
            dst[4352 + i] = hi4[2176 + i];
            dst[6528 + i] = lo4[2176 + i];
        }
    }

    const int aRow  = (lane & 7) + ((lane >> 3) & 1) * 8;
    const int aKoff = (lane >> 4) * 16;
    const uint32_t aHiBase = sb + S_A_HI + (16*wid + aRow)*APITCHB + aKoff;
    const uint32_t aLoBase = sb + S_A_LO + (16*wid + aRow)*APITCHB + aKoff;
    const int bRow4 = (lane & 7) + ((lane >> 4) & 1) * 8;
    const int bK4   = ((lane >> 3) & 1) * 16;
    const float* bias = (const float*)(smem + S_BIAS);
    const int r0 = 16*wid + (lane >> 2);
    const int cc = 2*(lane & 3);

    #pragma unroll 1
    for (int t = 0; t < 2; t++){
        __syncthreads();
        // ---- LayerNorm: 2 threads per row ----
        {
            const int row = tid >> 1, half = tid & 1;
            const float* xr = x + ((size_t)(blockIdx.x*256 + t*128 + row))*128 + half*64;
            float4 v[16];
            float s = 0.f, ss = 0.f;
            #pragma unroll
            for (int j = 0; j < 16; j++){
                v[j] = ((const float4*)xr)[j];
                s  += v[j].x + v[j].y + v[j].z + v[j].w;
                ss += v[j].x*v[j].x + v[j].y*v[j].y + v[j].z*v[j].z + v[j].w*v[j].w;
            }
            s  += __shfl_xor_sync(0xffffffffu, s, 1);
            ss += __shfl_xor_sync(0xffffffffu, ss, 1);
            const float m = s * (1.f/128.f);
            const float rstd = rsqrtf(ss*(1.f/128.f) - m*m + 1e-5f);
            #pragma unroll
            for (int j = 0; j < 16; j++){
                const int k0 = half*64 + j*4;
                float4 g4 = ((const float4*)gin)[k0>>2];
                float4 b4 = ((const float4*)bin)[k0>>2];
                float n0 = (v[j].x - m)*rstd*g4.x + b4.x;
                float n1 = (v[j].y - m)*rstd*g4.y + b4.y;
                float n2 = (v[j].z - m)*rstd*g4.z + b4.z;
                float n3 = (v[j].w - m)*rstd*g4.w + b4.w;
                __nv_bfloat16 h0 = __float2bfloat16_rn(n0), h1 = __float2bfloat16_rn(n1);
                __nv_bfloat16 h2 = __float2bfloat16_rn(n2), h3 = __float2bfloat16_rn(n3);
                __nv_bfloat162 hA; hA.x = h0; hA.y = h1;
                __nv_bfloat162 hB; hB.x = h2; hB.y = h3;
                __nv_bfloat162 lA, lB;
                lA.x = __float2bfloat16_rn(n0 - __bfloat162float(h0));
                lA.y = __float2bfloat16_rn(n1 - __bfloat162float(h1));
                lB.x = __float2bfloat16_rn(n2 - __bfloat162float(h2));
                lB.y = __float2bfloat16_rn(n3 - __bfloat162float(h3));
                char* ahp = smem + S_A_HI + row*APITCHB + k0*2;
                char* alp = smem + S_A_LO + row*APITCHB + k0*2;
                *(__nv_bfloat162*)(ahp)     = hA;
                *(__nv_bfloat162*)(ahp + 4) = hB;
                *(__nv_bfloat162*)(alp)     = lA;
                *(__nv_bfloat162*)(alp + 4) = lB;
            }
        }
        __syncthreads();

        const size_t gb = (size_t)blockIdx.x * 32768 + (size_t)t * 16384;

        #pragma unroll 1
        for (int colb_i = 0; colb_i < 2; colb_i++){
            const int colb = colb_i * 64;
            const uint32_t wKh = sb + S_W + (colb + bRow4)*APITCHB + bK4;
            const uint32_t wKl = wKh + 34816;
            const uint32_t wVh = wKh + 69632;
            const uint32_t wVl = wKh + 104448;

            float accK[8][4], accV[8][4];
            #pragma unroll
            for (int nt = 0; nt < 8; nt++)
                #pragma unroll
                for (int e = 0; e < 4; e++){ accK[nt][e]=0.f; accV[nt][e]=0.f; }

            #pragma unroll
            for (int kc = 0; kc < 8; kc++){
                const uint32_t ko = kc*32;
                uint32_t ah0,ah1,ah2,ah3, al0,al1,al2,al3;
                LDSM4(ah0,ah1,ah2,ah3, aHiBase + ko);
                LDSM4(al0,al1,al2,al3, aLoBase + ko);
                #pragma unroll
                for (int ntp = 0; ntp < 4; ntp++){
                    const uint32_t no = ntp*(16*APITCHB) + ko;
                    uint32_t bh0,bh1,bh2,bh3, bl0,bl1,bl2,bl3;
                    LDSM4(bh0,bh1,bh2,bh3, wKh + no);
                    LDSM4(bl0,bl1,bl2,bl3, wKl + no);
                    MMA16816(accK[2*ntp],   ah0,ah1,ah2,ah3, bh0,bh1);
                    MMA16816(accK[2*ntp],   ah0,ah1,ah2,ah3, bl0,bl1);
                    MMA16816(accK[2*ntp],   al0,al1,al2,al3, bh0,bh1);
                    MMA16816(accK[2*ntp+1], ah0,ah1,ah2,ah3, bh2,bh3);
                    MMA16816(accK[2*ntp+1], ah0,ah1,ah2,ah3, bl2,bl3);
                    MMA16816(accK[2*ntp+1], al0,al1,al2,al3, bh2,bh3);
                    LDSM4(bh0,bh1,bh2,bh3, wVh + no);
                    LDSM4(bl0,bl1,bl2,bl3, wVl + no);
                    MMA16816(accV[2*ntp],   ah0,ah1,ah2,ah3, bh0,bh1);
                    MMA16816(accV[2*ntp],   ah0,ah1,ah2,ah3, bl0,bl1);
                    MMA16816(accV[2*ntp],   al0,al1,al2,al3, bh0,bh1);
                    MMA16816(accV[2*ntp+1], ah0,ah1,ah2,ah3, bh2,bh3);
                    MMA16816(accV[2*ntp+1], ah0,ah1,ah2,ah3, bl2,bl3);
                    MMA16816(accV[2*ntp+1], al0,al1,al2,al3, bh2,bh3);
                }
            }

            #pragma unroll
            for (int nt = 0; nt < 8; nt++){
                const int col = colb + 8*nt + cc;
                float b0 = bias[col],       b1 = bias[col + 1];
                float2 v0; v0.x = accK[nt][0] + b0; v0.y = accK[nt][1] + b1;
                float2 v1; v1.x = accK[nt][2] + b0; v1.y = accK[nt][3] + b1;
                *(float2*)&g_keys[gb + (size_t)r0*128 + col]     = v0;
                *(float2*)&g_keys[gb + (size_t)(r0+8)*128 + col] = v1;
                b0 = bias[128 + col]; b1 = bias[128 + col + 1];
                float2 w0; w0.x = accV[nt][0] + b0; w0.y = accV[nt][1] + b1;
                float2 w1; w1.x = accV[nt][2] + b0; w1.y = accV[nt][3] + b1;
                *(float2*)&g_vals[gb + (size_t)r0*128 + col]     = w0;
                *(float2*)&g_vals[gb + (size_t)(r0+8)*128 + col] = w1;
            }
        }
    }
}

// ---------------- init: slots <- slots_init, q0, zero accumulators ----------------
__global__ __launch_bounds__(128) void init_q_kernel(
    const float* __restrict__ si,
    const float* __restrict__ Wq, const float* __restrict__ bq,
    const float* __restrict__ gs, const float* __restrict__ bs)
{
    __shared__ float sn[128];
    __shared__ float red[8];
    const int row = blockIdx.x, tid = threadIdx.x;
    const int lane = tid & 31, wrp = tid >> 5;
    float v = si[row*128 + tid];
    g_slots[row*128 + tid] = v;
    g_upd[row*128 + tid] = 0.f;
    if (tid == 0) g_rs[row] = 0.f;
    float s = v, ss = v*v;
    #pragma unroll
    for (int o = 16; o; o >>= 1){
        s  += __shfl_xor_sync(0xffffffffu, s, o);
        ss += __shfl_xor_sync(0xffffffffu, ss, o);
    }
    if (lane == 0){ red[wrp] = s; red[4+wrp] = ss; }
    __syncthreads();
    s  = red[0]+red[1]+red[2]+red[3];
    ss = red[4]+red[5]+red[6]+red[7];
    float m = s*(1.f/128.f);
    float rstd = rsqrtf(ss*(1.f/128.f) - m*m + 1e-5f);
    sn[tid] = (v - m)*rstd*gs[tid] + bs[tid];
    __syncthreads();
    float acc = bq[tid];
    const float4* wr  = (const float4*)(Wq + tid*128);
    const float4* sn4 = (const float4*)sn;
    #pragma unroll
    for (int e = 0; e < 32; e++){
        float4 w = wr[e], q = sn4[e];
        acc += w.x*q.x + w.y*q.y + w.z*q.z + w.w*q.w;
    }
    g_q[row*128 + tid] = acc * SCALE;
}

// ---------------- kernel 3: FUSED logits + softmax + (attn @ V) partials ----------------
// 128 threads; 8 lanes per token; 2 tokens per group per pass; grid = B * 32
__global__ __launch_bounds__(128) void fused_attn_upd_kernel()
{
    __shared__ float qp[NS*132];       // q transposed by d-segment, pitch 132
    __shared__ float ps[NS][132];      // softmax probs, padded
    const int tid = threadIdx.x;
    const int bb = blockIdx.x >> 5;
    const int n0 = (blockIdx.x & 31) * 128;

    // stage q: qp[seg][i*16 + k] = q[i][seg*16 + k]
    {
        const int sg = tid >> 4, k = tid & 15;
        #pragma unroll
        for (int i = 0; i < 8; i++)
            qp[sg*132 + i*16 + k] = g_q[bb*1024 + i*128 + tid];
    }
    __syncthreads();

    const int seg  = tid & 7;
    const int grp  = tid >> 3;          // 16 groups, each 2 tokens per pass
    const float* qseg = qp + seg*132;
    float srs_acc = 0.f;

    #pragma unroll 1
    for (int pass = 0; pass < 4; pass++){
        const int tok = pass*32 + grp*2;
        const float4* ka = (const float4*)(g_keys + (size_t)(bb*4096 + n0 + tok)*128 + seg*16);
        const float4* kb = (const float4*)((const float*)ka + 128);
        float4 a0 = ka[0], a1 = ka[1], a2 = ka[2], a3 = ka[3];
        float4 b0 = kb[0], b1 = kb[1], b2 = kb[2], b3 = kb[3];
        float la[8], lb[8];
        #pragma unroll
        for (int i = 0; i < 8; i++){
            const float4* q4 = (const float4*)(qseg + i*16);
            float4 q0 = q4[0], q1 = q4[1], q2 = q4[2], q3 = q4[3];
            la[i] = a0.x*q0.x + a0.y*q0.y + a0.z*q0.z + a0.w*q0.w
                  + a1.x*q1.x + a1.y*q1.y + a1.z*q1.z + a1.w*q1.w
                  + a2.x*q2.x + a2.y*q2.y + a2.z*q2.z + a2.w*q2.w
                  + a3.x*q3.x + a3.y*q3.y + a3.z*q3.z + a3.w*q3.w;
            lb[i] = b0.x*q0.x + b0.y*q0.y + b0.z*q0.z + b0.w*q0.w
                  + b1.x*q1.x + b1.y*q1.y + b1.z*q1.z + b1.w*q1.w
                  + b2.x*q2.x + b2.y*q2.y + b2.z*q2.z + b2.w*q2.w
                  + b3.x*q3.x + b3.y*q3.y + b3.z*q3.z + b3.w*q3.w;
        }
        #pragma unroll
        for (int i = 0; i < 8; i++){
            la[i] += __shfl_xor_sync(0xffffffffu, la[i], 1);
            la[i] += __shfl_xor_sync(0xffffffffu, la[i], 2);
            la[i] += __shfl_xor_sync(0xffffffffu, la[i], 4);
            lb[i] += __shfl_xor_sync(0xffffffffu, lb[i], 1);
            lb[i] += __shfl_xor_sync(0xffffffffu, lb[i], 2);
            lb[i] += __shfl_xor_sync(0xffffffffu, lb[i], 4);
        }
        float mxa = la[0], mxb = lb[0];
        #pragma unroll
        for (int i = 1; i < 8; i++){ mxa = fmaxf(mxa, la[i]); mxb = fmaxf(mxb, lb[i]); }
        float ea = __expf(la[seg] - mxa);
        float eb = __expf(lb[seg] - mxb);
        float sa = ea, sbv = eb;
        sa  += __shfl_xor_sync(0xffffffffu, sa, 1);
        sbv += __shfl_xor_sync(0xffffffffu, sbv, 1);
        sa  += __shfl_xor_sync(0xffffffffu, sa, 2);
        sbv += __shfl_xor_sync(0xffffffffu, sbv, 2);
        sa  += __shfl_xor_sync(0xffffffffu, sa, 4);
        sbv += __shfl_xor_sync(0xffffffffu, sbv, 4);
        float pa = ea*(1.f/sa) + 1e-8f;
        float pb = eb*(1.f/sbv) + 1e-8f;
        ps[seg][tok]   = pa;
        ps[seg][tok+1] = pb;
        srs_acc += pa + pb;
    }
    // reduce srs over the 4 same-seg lanes of each warp, then global atomic
    srs_acc += __shfl_xor_sync(0xffffffffu, srs_acc, 8);
    srs_acc += __shfl_xor_sync(0xffffffffu, srs_acc, 16);
    if ((tid & 31) < 8) atomicAdd(&g_rs[bb*8 + seg], srs_acc);
    __syncthreads();

    // ---- phase 2: partial updates = p^T @ V (coalesced over d = tid) ----
    float acc[8];
    #pragma unroll
    for (int i = 0; i < 8; i++) acc[i] = 0.f;
    const float* vp = g_vals + (size_t)(bb*4096 + n0)*128 + tid;
    #pragma unroll 4
    for (int n = 0; n < 128; n += 4){
        float v0 = vp[(n+0)*128];
        float v1 = vp[(n+1)*128];
        float v2 = vp[(n+2)*128];
        float v3 = vp[(n+3)*128];
        #pragma unroll
        for (int i = 0; i < 8; i++){
            const float4 a = *(const float4*)&ps[i][n];
            acc[i] += a.x*v0 + a.y*v1 + a.z*v2 + a.w*v3;
        }
    }
    #pragma unroll
    for (int i = 0; i < 8; i++)
        atomicAdd(&g_upd[(bb*8+i)*128 + tid], acc[i]);
}

// ---------------- kernel 4: GRU + LN + MLP + next-iter q; 4 rows per block ----------------
__global__ __launch_bounds__(128) void gru_mlp_q_kernel(
    const float* __restrict__ W_ih, const float* __restrict__ W_hh,
    const float* __restrict__ b_ih, const float* __restrict__ b_hh,
    const float* __restrict__ gm, const float* __restrict__ bm,
    const float* __restrict__ W1, const float* __restrict__ b1,
    const float* __restrict__ W2, const float* __restrict__ b2,
    const float* __restrict__ Wq, const float* __restrict__ bq,
    const float* __restrict__ gs, const float* __restrict__ bs)
{
    __shared__ float sa[4][128], sb[4][128], sc[4][128];
    __shared__ float red_s[4][4], red_ss[4][4];
    const int tid = threadIdx.x;
    const int lane = tid & 31, wrp = tid >> 5;
    const int r0 = blockIdx.x * 4;

    // ---- RACE FIX: read g_rs/g_upd into registers, sync, THEN zero ----
    float hv[4], uv[4], rsv[4];
    #pragma unroll
    for (int j = 0; j < 4; j++){
        const int row = r0 + j;
        rsv[j] = g_rs[row];
        uv[j]  = g_upd[row*128 + tid];
        hv[j]  = g_slots[row*128 + tid];
    }
    __syncthreads();   // all reads of g_rs complete before any thread zeroes it
    #pragma unroll
    for (int j = 0; j < 4; j++){
        const int row = r0 + j;
        sa[j][tid] = uv[j] / rsv[j];
        sb[j][tid] = hv[j];
        g_upd[row*128 + tid] = 0.f;
    }
    if (tid < 4) g_rs[r0 + tid] = 0.f;
    __syncthreads();

    float gi[3][4], gh[3][4];
    #pragma unroll 1
    for (int g = 0; g < 3; g++){
        const float4* wi = (const float4*)(W_ih + (g*128 + tid)*128);
        const float4* wh = (const float4*)(W_hh + (g*128 + tid)*128);
        const float bi = b_ih[g*128 + tid], bh = b_hh[g*128 + tid];
        float ai[4], ah[4];
        #pragma unroll
        for (int j = 0; j < 4; j++){ ai[j] = bi; ah[j] = bh; }
        #pragma unroll 4
        for (int e = 0; e < 32; e++){
            float4 w = wi[e];
            #pragma unroll
            for (int j = 0; j < 4; j++){
                float4 uu = ((const float4*)sa[j])[e];
                ai[j] += w.x*uu.x + w.y*uu.y + w.z*uu.z + w.w*uu.w;
            }
            float4 c = wh[e];
            #pragma unroll
            for (int j = 0; j < 4; j++){
                float4 pp = ((const float4*)sb[j])[e];
                ah[j] += c.x*pp.x + c.y*pp.y + c.z*pp.z + c.w*pp.w;
            }
        }
        #pragma unroll
        for (int j = 0; j < 4; j++){ gi[g][j] = ai[j]; gh[g][j] = ah[j]; }
    }

    float hnv[4];
    #pragma unroll
    for (int j = 0; j < 4; j++){
        float r = 1.f/(1.f + __expf(-(gi[0][j]+gh[0][j])));
        float z = 1.f/(1.f + __expf(-(gi[1][j]+gh[1][j])));
        float n = tanhf(gi[2][j] + r*gh[2][j]);
        hnv[j] = (1.f - z)*n + z*hv[j];
    }

    // LN(hn) -> sc
    #pragma unroll
    for (int j = 0; j < 4; j++){
        float s = hnv[j], ss = hnv[j]*hnv[j];
        #pragma unroll
        for (int o = 16; o; o >>= 1){
            s  += __shfl_xor_sync(0xffffffffu, s, o);
            ss += __shfl_xor_sync(0xffffffffu, ss, o);
        }
        if (lane == 0){ red_s[wrp][j] = s; red_ss[wrp][j] = ss; }
    }
    __syncthreads();
    #pragma unroll
    for (int j = 0; j < 4; j++){
        float s  = red_s[0][j]+red_s[1][j]+red_s[2][j]+red_s[3][j];
        float ss = red_ss[0][j]+red_ss[1][j]+red_ss[2][j]+red_ss[3][j];
        float m = s*(1.f/128.f);
        float rstd = rsqrtf(ss*(1.f/128.f) - m*m + 1e-5f);
        sc[j][tid] = (hnv[j] - m)*rstd*gm[tid] + bm[tid];
    }
    __syncthreads();

    // MLP layer 1 (relu) -> sa
    {
        const float4* w1 = (const float4*)(W1 + tid*128);
        const float bb1 = b1[tid];
        float hid[4];
        #pragma unroll
        for (int j = 0; j < 4; j++) hid[j] = bb1;
        #pragma unroll 4
        for (int e = 0; e < 32; e++){
            float4 w = w1[e];
            #pragma unroll
            for (int j = 0; j < 4; j++){
                float4 xx = ((const float4*)sc[j])[e];
                hid[j] += w.x*xx.x + w.y*xx.y + w.z*xx.z + w.w*xx.w;
            }
        }
        #pragma unroll
        for (int j = 0; j < 4; j++) sa[j][tid] = fmaxf(hid[j], 0.f);
    }
    __syncthreads();

    // MLP layer 2 -> out (residual)
    float outv[4];
    {
        const float4* w2 = (const float4*)(W2 + tid*128);
        const float bb2 = b2[tid];
        #pragma unroll
        for (int j = 0; j < 4; j++) outv[j] = hnv[j] + bb2;
        #pragma unroll 4
        for (int e = 0; e < 32; e++){
            float4 w = w2[e];
            #pragma unroll
            for (int j = 0; j < 4; j++){
                float4 xx = ((const float4*)sa[j])[e];
                outv[j] += w.x*xx.x + w.y*xx.y + w.z*xx.z + w.w*xx.w;
            }
        }
    }
    #pragma unroll
    for (int j = 0; j < 4; j++)
        g_slots[(r0+j)*128 + tid] = outv[j];
    __syncthreads();

    // LN(out) -> sb, then q projection
    #pragma unroll
    for (int j = 0; j < 4; j++){
        float s = outv[j], ss = outv[j]*outv[j];
        #pragma unroll
        for (int o = 16; o; o >>= 1){
            s  += __shfl_xor_sync(0xffffffffu, s, o);
            ss += __shfl_xor_sync(0xffffffffu, ss, o);
        }
        if (lane == 0){ red_s[wrp][j] = s; red_ss[wrp][j] = ss; }
    }
    __syncthreads();
    #pragma unroll
    for (int j = 0; j < 4; j++){
        float s  = red_s[0][j]+red_s[1][j]+red_s[2][j]+red_s[3][j];
        float ss = red_ss[0][j]+red_ss[1][j]+red_ss[2][j]+red_ss[3][j];
        float m = s*(1.f/128.f);
        float rstd = rsqrtf(ss*(1.f/128.f) - m*m + 1e-5f);
        sb[j][tid] = (outv[j] - m)*rstd*gs[tid] + bs[tid];
    }
    __syncthreads();
    {
        const float4* wq = (const float4*)(Wq + tid*128);
        const float bbq = bq[tid];
        float qa[4];
        #pragma unroll
        for (int j = 0; j < 4; j++) qa[j] = bbq;
        #pragma unroll 4
        for (int e = 0; e < 32; e++){
            float4 w = wq[e];
            #pragma unroll
            for (int j = 0; j < 4; j++){
                float4 xx = ((const float4*)sb[j])[e];
                qa[j] += w.x*xx.x + w.y*xx.y + w.z*xx.z + w.w*xx.w;
            }
        }
        #pragma unroll
        for (int j = 0; j < 4; j++)
            g_q[(r0+j)*128 + tid] = qa[j] * SCALE;
    }
}

// ---------------- launch ----------------
extern "C" void kernel_launch(void* const* d_in, const int* in_sizes, int n_in,
                              void* d_out, int out_size)
{
    const float* x    = (const float*)d_in[0];
    const float* si   = (const float*)d_in[1];
    const float* Wq   = (const float*)d_in[2];
    const float* bq   = (const float*)d_in[3];
    const float* Wk   = (const float*)d_in[4];
    const float* bk   = (const float*)d_in[5];
    const float* Wv   = (const float*)d_in[6];
    const float* bv   = (const float*)d_in[7];
    const float* gin  = (const float*)d_in[8];
    const float* bin  = (const float*)d_in[9];
    const float* gsl  = (const float*)d_in[10];
    const float* bsl  = (const float*)d_in[11];
    const float* gm   = (const float*)d_in[12];
    const float* bm   = (const float*)d_in[13];
    const float* W1   = (const float*)d_in[14];
    const float* b1   = (const float*)d_in[15];
    const float* W2   = (const float*)d_in[16];
    const float* b2   = (const float*)d_in[17];
    const float* W_ih = (const float*)d_in[18];
    const float* W_hh = (const float*)d_in[19];
    const float* b_ih = (const float*)d_in[20];
    const float* b_hh = (const float*)d_in[21];

    static bool attr_set = false;
    if (!attr_set){
        cudaFuncSetAttribute(ln_kv_mma_kernel,
                             cudaFuncAttributeMaxDynamicSharedMemorySize, S_TOTAL);
        attr_set = true;
    }

    prep_w_kernel<<<128, 256>>>(Wk, Wv);
    init_q_kernel<<<512, 128>>>(si, Wq, bq, gsl, bsl);
    ln_kv_mma_kernel<<<1024, 256, S_TOTAL>>>(x, bk, bv, gin, bin);
    for (int it = 0; it < 3; it++){
        fused_attn_upd_kernel<<<2048, 128>>>();
        gru_mlp_q_kernel<<<128, 128>>>(W_ih, W_hh, b_ih, b_hh, gm, bm,
                                       W1, b1, W2, b2, Wq, bq, gsl, bsl);
    }
    export_kernel<<<256, 256>>>((float*)d_out);
}